// round 1
// baseline (speedup 1.0000x reference)
#include <cuda_runtime.h>
#include <cstdint>

#define NN 50000
#define FF 128
#define DD 256
#define EE 800000
#define GG 128
#define BN_EPS 1e-5f

// ---------------- static scratch (no runtime allocation allowed) ----------------
__device__ float g_agg[(size_t)NN * DD];
__device__ float g_hid[(size_t)NN * DD];
__device__ float g_h2 [(size_t)NN * DD];
__device__ float g_nrm[(size_t)NN * DD];
__device__ float g_stats[2 * DD];   // [0:256) sum, [256:512) sumsq
__device__ int   g_idx64;           // 1 if index arrays are int64, 0 if int32

// ---------------- small helpers ----------------
__device__ __forceinline__ unsigned long long pack2(float a, float b) {
    unsigned long long r;
    asm("mov.b64 %0, {%1, %2};" : "=l"(r) : "f"(a), "f"(b));
    return r;
}
__device__ __forceinline__ void unpack2(unsigned long long v, float& a, float& b) {
    asm("mov.b64 {%0, %1}, %2;" : "=f"(a), "=f"(b) : "l"(v));
}
__device__ __forceinline__ unsigned long long fma2(unsigned long long a,
                                                   unsigned long long b,
                                                   unsigned long long c) {
    unsigned long long d;
    asm("fma.rn.f32x2 %0, %1, %2, %3;" : "=l"(d) : "l"(a), "l"(b), "l"(c));
    return d;
}
__device__ __forceinline__ void red_add_v4(float* p, float4 v) {
    asm volatile("red.global.add.v4.f32 [%0], {%1, %2, %3, %4};"
                 :: "l"(p), "f"(v.x), "f"(v.y), "f"(v.z), "f"(v.w) : "memory");
}

// ---------------- index dtype detection ----------------
// Reference requests int64 indices, but JAX without x64 enabled silently emits
// int32. Values are < 50000, so for int64 every odd 32-bit word is 0.
__global__ void detect_k(const int* ei) {
    int allz = 1;
    for (int i = 1; i < 512; i += 2) {
        if (ei[i] != 0) { allz = 0; break; }
    }
    g_idx64 = allz;
}

__device__ __forceinline__ int load_index(const void* p, long long i, int is64) {
    if (is64) return (int)((const long long*)p)[i];
    return ((const int*)p)[i];
}

// ---------------- edge scatter-add: agg[dst] += h[src] ----------------
// One thread per (edge, float4-chunk). DIMV = d/4 chunks per row.
template<int DIMV, int LOG2V>
__global__ void scatter_k(const float* __restrict__ x, const void* __restrict__ ei,
                          float* __restrict__ agg) {
    long long t = (long long)blockIdx.x * blockDim.x + threadIdx.x;
    long long e = t >> LOG2V;
    if (e >= EE) return;
    int c = (int)(t & (DIMV - 1));
    int is64 = g_idx64;
    int src = load_index(ei, e, is64);
    int dst = load_index(ei, EE + e, is64);
    float4 v = __ldg((const float4*)x + (long long)src * DIMV + c);
    red_add_v4(agg + ((long long)dst * DIMV + c) * 4, v);
}

// ---------------- SGEMM: C = relu((A0 [+ A1]) @ B + bias) ----------------
// A: [NN, K] row-major, B: [K, 256] row-major, C: [NN, 256].
// 128x128 tile, BK=16, 256 threads, 8x8 micro-tile, packed f32x2 FMA.
template<int K>
__global__ void __launch_bounds__(256, 2)
gemm_k(const float* __restrict__ A0, const float* __restrict__ A1,
       const float* __restrict__ B, const float* __restrict__ bias,
       float* __restrict__ C) {
    __shared__ float As[16][132];
    __shared__ float Bs[16][132];
    const int tid = threadIdx.x;
    const int m0  = blockIdx.x * 128;
    const int n0  = blockIdx.y * 128;
    const int r0  = (tid >> 4) * 8;
    const int c0  = (tid & 15) * 8;

    float breg[8];
#pragma unroll
    for (int j = 0; j < 8; j++) breg[j] = bias[n0 + c0 + j];

    unsigned long long acc[8][4];
#pragma unroll
    for (int i = 0; i < 8; i++)
#pragma unroll
        for (int j = 0; j < 4; j++) acc[i][j] = 0ull;

    for (int kt = 0; kt < K / 16; kt++) {
#pragma unroll
        for (int it = 0; it < 2; it++) {
            int i   = it * 256 + tid;
            // A tile: 128 rows x 16 k, float4 granules, stored k-major (transposed)
            int row = i >> 2;
            int kq  = i & 3;
            float4 v = make_float4(0.f, 0.f, 0.f, 0.f);
            int gr = m0 + row;
            if (gr < NN) {
                v = __ldg((const float4*)A0 + (long long)gr * (K / 4) + kt * 4 + kq);
                if (A1) {
                    float4 w = __ldg((const float4*)A1 + (long long)gr * (K / 4) + kt * 4 + kq);
                    v.x += w.x; v.y += w.y; v.z += w.z; v.w += w.w;
                }
            }
            As[kq * 4 + 0][row] = v.x;
            As[kq * 4 + 1][row] = v.y;
            As[kq * 4 + 2][row] = v.z;
            As[kq * 4 + 3][row] = v.w;
            // B tile: 16 k-rows x 128 cols
            int kr = i >> 5;
            int nc = i & 31;
            float4 bv = __ldg((const float4*)B + (long long)(kt * 16 + kr) * 64 + (n0 >> 2) + nc);
            *(float4*)&Bs[kr][nc * 4] = bv;
        }
        __syncthreads();
#pragma unroll
        for (int k = 0; k < 16; k++) {
            float4 a0 = *(const float4*)&As[k][r0];
            float4 a1 = *(const float4*)&As[k][r0 + 4];
            float4 b0 = *(const float4*)&Bs[k][c0];
            float4 b1 = *(const float4*)&Bs[k][c0 + 4];
            unsigned long long bp[4] = { pack2(b0.x, b0.y), pack2(b0.z, b0.w),
                                         pack2(b1.x, b1.y), pack2(b1.z, b1.w) };
            float av[8] = { a0.x, a0.y, a0.z, a0.w, a1.x, a1.y, a1.z, a1.w };
#pragma unroll
            for (int i = 0; i < 8; i++) {
                unsigned long long ad = pack2(av[i], av[i]);
#pragma unroll
                for (int j = 0; j < 4; j++) acc[i][j] = fma2(ad, bp[j], acc[i][j]);
            }
        }
        __syncthreads();
    }

#pragma unroll
    for (int i = 0; i < 8; i++) {
        int gr = m0 + r0 + i;
        if (gr < NN) {
            float o[8];
#pragma unroll
            for (int j = 0; j < 4; j++) unpack2(acc[i][j], o[2 * j], o[2 * j + 1]);
#pragma unroll
            for (int j = 0; j < 8; j++) o[j] = fmaxf(o[j] + breg[j], 0.f);
            *(float4*)&C[(long long)gr * 256 + n0 + c0]     = make_float4(o[0], o[1], o[2], o[3]);
            *(float4*)&C[(long long)gr * 256 + n0 + c0 + 4] = make_float4(o[4], o[5], o[6], o[7]);
        }
    }
}

// ---------------- batchnorm statistics ----------------
__global__ void bn_stats_k(const float* __restrict__ h) {
    int c = threadIdx.x;                       // 256 threads = one column each
    int rows_per = (NN + gridDim.x - 1) / gridDim.x;
    int r0 = blockIdx.x * rows_per;
    int r1 = min(NN, r0 + rows_per);
    float s = 0.f, sq = 0.f;
    for (int r = r0; r < r1; r++) {
        float v = h[(long long)r * 256 + c];
        s  += v;
        sq += v * v;
    }
    atomicAdd(&g_stats[c], s);
    atomicAdd(&g_stats[256 + c], sq);
}

// ---------------- batchnorm apply (elementwise, float4) ----------------
__global__ void bn_apply_k(const float* __restrict__ h, const float* __restrict__ gamma,
                           const float* __restrict__ beta, float* __restrict__ o) {
    long long t = (long long)blockIdx.x * blockDim.x + threadIdx.x;   // float4 index
    if (t >= (long long)NN * 64) return;
    int c4 = ((int)t & 63) * 4;
    float4 v = ((const float4*)h)[t];
    float4 r;
    const float invn = 1.f / (float)NN;
#pragma unroll
    for (int j = 0; j < 4; j++) {
        int c = c4 + j;
        float mean = g_stats[c] * invn;
        float var  = g_stats[256 + c] * invn - mean * mean;
        float sc   = gamma[c] * rsqrtf(var + BN_EPS);
        float sh   = beta[c] - mean * sc;
        float x    = (&v.x)[j];
        (&r.x)[j]  = fmaf(x, sc, sh);
    }
    ((float4*)o)[t] = r;
}

// ---------------- global add pool (batch is sorted) ----------------
__device__ int lower_bound_g(const void* b, int v, int is64) {
    int lo = 0, hi = NN;
    while (lo < hi) {
        int mid = (lo + hi) >> 1;
        if (load_index(b, mid, is64) < v) lo = mid + 1; else hi = mid;
    }
    return lo;
}

__global__ void pool_k(const float* __restrict__ h, const void* __restrict__ batch,
                       float* __restrict__ out) {
    __shared__ int slo, shi;
    int g = blockIdx.x;
    if (threadIdx.x == 0) {
        int is64 = g_idx64;
        slo = lower_bound_g(batch, g, is64);
        shi = lower_bound_g(batch, g + 1, is64);
    }
    __syncthreads();
    int c = threadIdx.x;
    float s = 0.f;
    for (int r = slo; r < shi; r++) s += h[(long long)r * 256 + c];
    out[g * 256 + c] = s;
}

// ---------------- launch ----------------
extern "C" void kernel_launch(void* const* d_in, const int* in_sizes, int n_in,
                              void* d_out, int out_size) {
    const float* x     = (const float*)d_in[0];
    const void*  ei    = d_in[1];
    const void*  batch = d_in[2];

    float *agg, *hid, *h2, *nrm, *stats;
    cudaGetSymbolAddress((void**)&agg,   g_agg);
    cudaGetSymbolAddress((void**)&hid,   g_hid);
    cudaGetSymbolAddress((void**)&h2,    g_h2);
    cudaGetSymbolAddress((void**)&nrm,   g_nrm);
    cudaGetSymbolAddress((void**)&stats, g_stats);

    detect_k<<<1, 1>>>((const int*)ei);

    const float* in_feat = x;
    for (int l = 0; l < 3; l++) {
        const float* w1    = (const float*)d_in[3 + 6 * l];
        const float* b1    = (const float*)d_in[4 + 6 * l];
        const float* w2    = (const float*)d_in[5 + 6 * l];
        const float* b2    = (const float*)d_in[6 + 6 * l];
        const float* gamma = (const float*)d_in[7 + 6 * l];
        const float* beta  = (const float*)d_in[8 + 6 * l];
        const int d = (l == 0) ? FF : DD;

        cudaMemsetAsync(agg, 0, (size_t)NN * d * sizeof(float));

        if (l == 0) {
            long long tw = (long long)EE * 32;
            scatter_k<32, 5><<<(unsigned)((tw + 255) / 256), 256>>>(in_feat, ei, agg);
        } else {
            long long tw = (long long)EE * 64;
            scatter_k<64, 6><<<(unsigned)((tw + 255) / 256), 256>>>(in_feat, ei, agg);
        }

        dim3 gg((NN + 127) / 128, 2);
        if (l == 0) gemm_k<128><<<gg, 256>>>(in_feat, agg, w1, b1, hid);
        else        gemm_k<256><<<gg, 256>>>(in_feat, agg, w1, b1, hid);
        gemm_k<256><<<gg, 256>>>(hid, nullptr, w2, b2, h2);

        cudaMemsetAsync(stats, 0, 2 * DD * sizeof(float));
        bn_stats_k<<<250, 256>>>(h2);
        bn_apply_k<<<(int)(((long long)NN * 64 + 255) / 256), 256>>>(h2, gamma, beta, nrm);

        in_feat = nrm;
    }

    pool_k<<<GG, 256>>>(nrm, batch, (float*)d_out);
}

// round 3
// speedup vs baseline: 2.0857x; 2.0857x over previous
#include <cuda_runtime.h>
#include <cstdint>

#define NN 50000
#define FF 128
#define DD 256
#define EE 800000
#define GG 128
#define BN_EPS 1e-5f

// ---------------- static scratch ----------------
__device__ float g_agg[(size_t)NN * DD];
__device__ float g_hid[(size_t)NN * DD];
__device__ float g_h2 [(size_t)NN * DD];
__device__ float g_nrm[(size_t)NN * DD];
__device__ float g_stats[2 * DD];
__device__ int   g_idx64;
// split weights: slot s -> [256][K/2] packed bf16x2, hi and lo
__device__ uint32_t g_bhi[6 * 256 * 128];
__device__ uint32_t g_blo[6 * 256 * 128];
// CSR
__device__ int g_deg[NN];
__device__ int g_off[NN + 1];
__device__ int g_wp [NN];
__device__ int g_part[256];
__device__ int g_srcs[EE];

// ---------------- helpers ----------------
// split two floats (e = even-k, o = odd-k) into packed bf16x2 hi and lo.
// pack layout: lower 16 bits = even-k (first element), upper = odd-k.
__device__ __forceinline__ void split2(float e, float o, uint32_t& hi, uint32_t& lo) {
    uint32_t h;
    asm("cvt.rn.bf16x2.f32 %0, %1, %2;" : "=r"(h) : "f"(o), "f"(e));
    float ef = __uint_as_float(h << 16);
    float of = __uint_as_float(h & 0xffff0000u);
    uint32_t l;
    asm("cvt.rn.bf16x2.f32 %0, %1, %2;" : "=r"(l) : "f"(o - of), "f"(e - ef));
    hi = h; lo = l;
}
__device__ __forceinline__ void mma_bf16(float* d, const uint32_t* a, const uint32_t* b) {
    asm volatile("mma.sync.aligned.m16n8k16.row.col.f32.bf16.bf16.f32 "
                 "{%0,%1,%2,%3}, {%4,%5,%6,%7}, {%8,%9}, {%0,%1,%2,%3};"
                 : "+f"(d[0]), "+f"(d[1]), "+f"(d[2]), "+f"(d[3])
                 : "r"(a[0]), "r"(a[1]), "r"(a[2]), "r"(a[3]), "r"(b[0]), "r"(b[1]));
}
__device__ __forceinline__ void cp16(uint32_t dst, const void* src) {
    asm volatile("cp.async.cg.shared.global [%0], [%1], 16;" :: "r"(dst), "l"(src));
}

// ---------------- index dtype detection ----------------
__global__ void detect_k(const int* ei) {
    int allz = 1;
    for (int i = 1; i < 512; i += 2)
        if (ei[i] != 0) { allz = 0; break; }
    g_idx64 = allz;
}
__device__ __forceinline__ int load_index(const void* p, long long i, int is64) {
    if (is64) return (int)((const long long*)p)[i];
    return ((const int*)p)[i];
}

// ---------------- CSR build ----------------
__global__ void hist_k(const void* ei) {
    int e = blockIdx.x * 256 + threadIdx.x;
    if (e >= EE) return;
    int dst = load_index(ei, EE + e, g_idx64);
    atomicAdd(&g_deg[dst], 1);
}
__global__ void scan1_k() {            // grid 196, block 256: block sums
    __shared__ int sm[256];
    int i = blockIdx.x * 256 + threadIdx.x;
    sm[threadIdx.x] = (i < NN) ? g_deg[i] : 0;
    __syncthreads();
    for (int st = 128; st > 0; st >>= 1) {
        if (threadIdx.x < st) sm[threadIdx.x] += sm[threadIdx.x + st];
        __syncthreads();
    }
    if (threadIdx.x == 0) g_part[blockIdx.x] = sm[0];
}
__global__ void scan2_k(int nb) {      // 1 block: exclusive scan of partials in smem
    __shared__ int sm[256];
    int t = threadIdx.x;
    sm[t] = (t < nb) ? g_part[t] : 0;
    __syncthreads();
    if (t == 0) {
        int acc = 0;
        for (int b = 0; b < nb; b++) { int v = sm[b]; sm[b] = acc; acc += v; }
        g_off[NN] = EE;
    }
    __syncthreads();
    if (t < nb) g_part[t] = sm[t];
}
__global__ void scan3_k() {            // per-block inclusive scan -> offsets
    __shared__ int sm[256];
    int i = blockIdx.x * 256 + threadIdx.x;
    int v = (i < NN) ? g_deg[i] : 0;
    sm[threadIdx.x] = v;
    __syncthreads();
    for (int st = 1; st < 256; st <<= 1) {
        int t = (threadIdx.x >= st) ? sm[threadIdx.x - st] : 0;
        __syncthreads();
        sm[threadIdx.x] += t;
        __syncthreads();
    }
    if (i < NN) {
        int off = g_part[blockIdx.x] + sm[threadIdx.x] - v;
        g_off[i] = off;
        g_wp[i]  = off;
    }
}
__global__ void fill_k(const void* ei) {
    int e = blockIdx.x * 256 + threadIdx.x;
    if (e >= EE) return;
    int is64 = g_idx64;
    int src = load_index(ei, e, is64);
    int dst = load_index(ei, EE + e, is64);
    int p = atomicAdd(&g_wp[dst], 1);
    g_srcs[p] = src;
}

// ---------------- aggregation: agg[r] = x[r] + sum_{j in N(r)} x[j] ----------------
template<int DIMV>
__global__ void agg_k(const float* __restrict__ x, float* __restrict__ agg) {
    constexpr int RPB = 256 / DIMV;
    int r = blockIdx.x * RPB + threadIdx.x / DIMV;
    int c = threadIdx.x & (DIMV - 1);
    if (r >= NN) return;
    const float4* x4 = (const float4*)x;
    float4 s = x4[(size_t)r * DIMV + c];
    int i1 = g_off[r + 1];
    for (int i = g_off[r]; i < i1; i++) {
        int src = g_srcs[i];
        float4 v = __ldg(&x4[(size_t)src * DIMV + c]);
        s.x += v.x; s.y += v.y; s.z += v.z; s.w += v.w;
    }
    ((float4*)agg)[(size_t)r * DIMV + c] = s;
}

// ---------------- weight pre-split: w [K][256] -> [256][K/2] packed hi/lo ----------------
__global__ void convw_k(const float* __restrict__ w, uint32_t* __restrict__ bhi,
                        uint32_t* __restrict__ blo, int kpc) {
    int t = blockIdx.x * 256 + threadIdx.x;
    if (t >= 256 * kpc) return;
    int n = t / kpc, kp = t - n * kpc;
    float e = w[(2 * kp)     * 256 + n];
    float o = w[(2 * kp + 1) * 256 + n];
    uint32_t h, l;
    split2(e, o, h, l);
    bhi[n * kpc + kp] = h;
    blo[n * kpc + kp] = l;
}

// ---------------- bf16x3 tensor GEMM: C = relu(A @ B + bias) ----------------
// A [NN,K] f32 row-major; B pre-split packed [256][K/2]; C [NN,256].
// 128x128 tile, BK=16, 8 warps (2x4), warp 64x32, mma m16n8k16.
template<int K>
__global__ void __launch_bounds__(256)
gemm_bf(const float* __restrict__ A, const uint32_t* __restrict__ Bhi,
        const uint32_t* __restrict__ Blo, const float* __restrict__ bias,
        float* __restrict__ C) {
    constexpr int NT = K / 16, KP = K / 2;
    __shared__ uint32_t As_hi[128][12], As_lo[128][12];
    __shared__ uint32_t Bs_hi[2][128][12], Bs_lo[2][128][12];

    const int tid  = threadIdx.x;
    const int lane = tid & 31, w = tid >> 5;
    const int wm = (w >> 2) * 64, wn = (w & 3) * 32;
    const int m0 = blockIdx.x * 128, n0 = blockIdx.y * 128;
    const int lq = lane >> 2, lr = lane & 3;
    const int arow = tid >> 1, akh = tid & 1;   // A: row, k-half (8 floats)
    const bool avalid = (m0 + arow) < NN;

    float acc[4][4][4];
#pragma unroll
    for (int i = 0; i < 4; i++)
#pragma unroll
        for (int j = 0; j < 4; j++)
#pragma unroll
            for (int r = 0; r < 4; r++) acc[i][j][r] = 0.f;

    float rA[8];
    auto ldgA = [&](int kt) {
        if (avalid) {
            const float4* p = (const float4*)(A + (size_t)(m0 + arow) * K + kt * 16 + akh * 8);
            float4 v0 = __ldg(p), v1 = __ldg(p + 1);
            rA[0] = v0.x; rA[1] = v0.y; rA[2] = v0.z; rA[3] = v0.w;
            rA[4] = v1.x; rA[5] = v1.y; rA[6] = v1.z; rA[7] = v1.w;
        } else {
#pragma unroll
            for (int j = 0; j < 8; j++) rA[j] = 0.f;
        }
    };
    auto stsA = [&]() {
        uint32_t h[4], l[4];
#pragma unroll
        for (int j = 0; j < 4; j++) split2(rA[2 * j], rA[2 * j + 1], h[j], l[j]);
        *(uint4*)&As_hi[arow][akh * 4] = make_uint4(h[0], h[1], h[2], h[3]);
        *(uint4*)&As_lo[arow][akh * 4] = make_uint4(l[0], l[1], l[2], l[3]);
    };
    auto cpB = [&](int kt, int s) {
        size_t o = (size_t)(n0 + arow) * KP + kt * 8 + akh * 4;
        cp16((uint32_t)__cvta_generic_to_shared(&Bs_hi[s][arow][akh * 4]), Bhi + o);
        cp16((uint32_t)__cvta_generic_to_shared(&Bs_lo[s][arow][akh * 4]), Blo + o);
    };

    ldgA(0);
    cpB(0, 0);
    asm volatile("cp.async.commit_group;");

    for (int kt = 0; kt < NT; kt++) {
        const int s = kt & 1;
        stsA();
        if (kt + 1 < NT) ldgA(kt + 1);
        asm volatile("cp.async.wait_group 0;");
        __syncthreads();
        if (kt + 1 < NT) {
            cpB(kt + 1, s ^ 1);
            asm volatile("cp.async.commit_group;");
        }
        uint32_t ah[4][4], al[4][4], bh[4][2], bl[4][2];
#pragma unroll
        for (int mi = 0; mi < 4; mi++) {
            int r = wm + mi * 16 + lq;
            ah[mi][0] = As_hi[r][lr];     ah[mi][1] = As_hi[r + 8][lr];
            ah[mi][2] = As_hi[r][lr + 4]; ah[mi][3] = As_hi[r + 8][lr + 4];
            al[mi][0] = As_lo[r][lr];     al[mi][1] = As_lo[r + 8][lr];
            al[mi][2] = As_lo[r][lr + 4]; al[mi][3] = As_lo[r + 8][lr + 4];
        }
#pragma unroll
        for (int ni = 0; ni < 4; ni++) {
            int c = wn + ni * 8 + lq;
            bh[ni][0] = Bs_hi[s][c][lr]; bh[ni][1] = Bs_hi[s][c][lr + 4];
            bl[ni][0] = Bs_lo[s][c][lr]; bl[ni][1] = Bs_lo[s][c][lr + 4];
        }
#pragma unroll
        for (int mi = 0; mi < 4; mi++)
#pragma unroll
            for (int ni = 0; ni < 4; ni++) {
                mma_bf16(acc[mi][ni], ah[mi], bh[ni]);
                mma_bf16(acc[mi][ni], al[mi], bh[ni]);
                mma_bf16(acc[mi][ni], ah[mi], bl[ni]);
            }
        __syncthreads();
    }

#pragma unroll
    for (int mi = 0; mi < 4; mi++)
#pragma unroll
        for (int half = 0; half < 2; half++) {
            int row = m0 + wm + mi * 16 + lq + half * 8;
            if (row < NN) {
#pragma unroll
                for (int ni = 0; ni < 4; ni++) {
                    int col = n0 + wn + ni * 8 + 2 * lr;
                    float2 bv = *(const float2*)&bias[col];
                    float v0 = fmaxf(acc[mi][ni][half * 2 + 0] + bv.x, 0.f);
                    float v1 = fmaxf(acc[mi][ni][half * 2 + 1] + bv.y, 0.f);
                    *(float2*)&C[(size_t)row * 256 + col] = make_float2(v0, v1);
                }
            }
        }
}

// ---------------- batchnorm ----------------
__global__ void bn_stats_k(const float* __restrict__ h) {
    int c = threadIdx.x;
    int rows_per = (NN + gridDim.x - 1) / gridDim.x;
    int r0 = blockIdx.x * rows_per;
    int r1 = min(NN, r0 + rows_per);
    float s = 0.f, sq = 0.f;
    for (int r = r0; r < r1; r++) {
        float v = h[(size_t)r * 256 + c];
        s += v; sq += v * v;
    }
    atomicAdd(&g_stats[c], s);
    atomicAdd(&g_stats[256 + c], sq);
}
__global__ void bn_apply_k(const float* __restrict__ h, const float* __restrict__ gamma,
                           const float* __restrict__ beta, float* __restrict__ o) {
    long long t = (long long)blockIdx.x * blockDim.x + threadIdx.x;
    if (t >= (long long)NN * 64) return;
    int c4 = ((int)t & 63) * 4;
    float4 v = ((const float4*)h)[t];
    float4 r;
    const float invn = 1.f / (float)NN;
#pragma unroll
    for (int j = 0; j < 4; j++) {
        int c = c4 + j;
        float mean = g_stats[c] * invn;
        float var  = g_stats[256 + c] * invn - mean * mean;
        float sc   = gamma[c] * rsqrtf(var + BN_EPS);
        float sh   = beta[c] - mean * sc;
        (&r.x)[j]  = fmaf((&v.x)[j], sc, sh);
    }
    ((float4*)o)[t] = r;
}

// ---------------- global add pool ----------------
__device__ int lower_bound_g(const void* b, int v, int is64) {
    int lo = 0, hi = NN;
    while (lo < hi) {
        int mid = (lo + hi) >> 1;
        if (load_index(b, mid, is64) < v) lo = mid + 1; else hi = mid;
    }
    return lo;
}
__global__ void pool_k(const float* __restrict__ h, const void* __restrict__ batch,
                       float* __restrict__ out) {
    __shared__ int slo, shi;
    int g = blockIdx.x;
    if (threadIdx.x == 0) {
        int is64 = g_idx64;
        slo = lower_bound_g(batch, g, is64);
        shi = lower_bound_g(batch, g + 1, is64);
    }
    __syncthreads();
    int c = threadIdx.x;
    float s = 0.f;
    for (int r = slo; r < shi; r++) s += h[(size_t)r * 256 + c];
    out[g * 256 + c] = s;
}

// ---------------- launch ----------------
extern "C" void kernel_launch(void* const* d_in, const int* in_sizes, int n_in,
                              void* d_out, int out_size) {
    const float* x     = (const float*)d_in[0];
    const void*  ei    = d_in[1];
    const void*  batch = d_in[2];

    float *agg, *hid, *h2, *nrm, *stats;
    uint32_t *bhi, *blo;
    int *deg;
    cudaGetSymbolAddress((void**)&agg,   g_agg);
    cudaGetSymbolAddress((void**)&hid,   g_hid);
    cudaGetSymbolAddress((void**)&h2,    g_h2);
    cudaGetSymbolAddress((void**)&nrm,   g_nrm);
    cudaGetSymbolAddress((void**)&stats, g_stats);
    cudaGetSymbolAddress((void**)&bhi,   g_bhi);
    cudaGetSymbolAddress((void**)&blo,   g_blo);
    cudaGetSymbolAddress((void**)&deg,   g_deg);

    detect_k<<<1, 1>>>((const int*)ei);

    // CSR build (edge_index is layer-invariant)
    const int NB = (NN + 255) / 256;   // 196
    cudaMemsetAsync(deg, 0, NN * sizeof(int));
    hist_k<<<(EE + 255) / 256, 256>>>(ei);
    scan1_k<<<NB, 256>>>();
    scan2_k<<<1, 256>>>(NB);
    scan3_k<<<NB, 256>>>();
    fill_k<<<(EE + 255) / 256, 256>>>(ei);

    // pre-split all weights
    for (int l = 0; l < 3; l++) {
        int k1 = (l == 0) ? FF : DD;
        convw_k<<<(256 * (k1 / 2) + 255) / 256, 256>>>(
            (const float*)d_in[3 + 6 * l], bhi + (2 * l) * 256 * 128,
            blo + (2 * l) * 256 * 128, k1 / 2);
        convw_k<<<(256 * 128 + 255) / 256, 256>>>(
            (const float*)d_in[5 + 6 * l], bhi + (2 * l + 1) * 256 * 128,
            blo + (2 * l + 1) * 256 * 128, 128);
    }

    const float* in_feat = x;
    for (int l = 0; l < 3; l++) {
        const float* b1    = (const float*)d_in[4 + 6 * l];
        const float* b2    = (const float*)d_in[6 + 6 * l];
        const float* gamma = (const float*)d_in[7 + 6 * l];
        const float* beta  = (const float*)d_in[8 + 6 * l];

        if (l == 0) agg_k<32><<<(NN + 7) / 8, 256>>>(in_feat, agg);
        else        agg_k<64><<<(NN + 3) / 4, 256>>>(in_feat, agg);

        dim3 gg((NN + 127) / 128, 2);
        const uint32_t* w1h = bhi + (2 * l) * 256 * 128;
        const uint32_t* w1l = blo + (2 * l) * 256 * 128;
        const uint32_t* w2h = bhi + (2 * l + 1) * 256 * 128;
        const uint32_t* w2l = blo + (2 * l + 1) * 256 * 128;
        if (l == 0) gemm_bf<128><<<gg, 256>>>(agg, w1h, w1l, b1, hid);
        else        gemm_bf<256><<<gg, 256>>>(agg, w1h, w1l, b1, hid);
        gemm_bf<256><<<gg, 256>>>(hid, w2h, w2l, b2, h2);

        cudaMemsetAsync(stats, 0, 2 * DD * sizeof(float));
        bn_stats_k<<<250, 256>>>(h2);
        bn_apply_k<<<(int)(((long long)NN * 64 + 255) / 256), 256>>>(h2, gamma, beta, nrm);

        in_feat = nrm;
    }

    pool_k<<<GG, 256>>>(nrm, batch, (float*)d_out);
}

// round 4
// speedup vs baseline: 2.4366x; 1.1682x over previous
#include <cuda_runtime.h>
#include <cstdint>

#define NN 50000
#define FF 128
#define DD 256
#define EE 800000
#define GG 128
#define BN_EPS 1e-5f

// ---------------- static scratch ----------------
__device__ float g_agg[(size_t)NN * DD];
__device__ float g_hid[(size_t)NN * DD];
__device__ float g_h2 [(size_t)NN * DD];
__device__ float g_stats[2 * DD];   // sum, sumsq
__device__ float g_scsh[2 * DD];    // sc, sh
__device__ int   g_idx64;
// split weights: slot s -> [256][K/2] packed bf16x2, hi and lo
__device__ uint32_t g_bhi[6 * 256 * 128];
__device__ uint32_t g_blo[6 * 256 * 128];
// CSR
__device__ int g_deg[NN];
__device__ int g_off[NN + 1];
__device__ int g_wp [NN];
__device__ int g_part[256];
__device__ int g_srcs[EE];

// ---------------- helpers ----------------
__device__ __forceinline__ void split2(float e, float o, uint32_t& hi, uint32_t& lo) {
    uint32_t h;
    asm("cvt.rn.bf16x2.f32 %0, %1, %2;" : "=r"(h) : "f"(o), "f"(e));
    float ef = __uint_as_float(h << 16);
    float of = __uint_as_float(h & 0xffff0000u);
    uint32_t l;
    asm("cvt.rn.bf16x2.f32 %0, %1, %2;" : "=r"(l) : "f"(o - of), "f"(e - ef));
    hi = h; lo = l;
}
__device__ __forceinline__ void mma_bf16(float* d, const uint32_t* a, const uint32_t* b) {
    asm volatile("mma.sync.aligned.m16n8k16.row.col.f32.bf16.bf16.f32 "
                 "{%0,%1,%2,%3}, {%4,%5,%6,%7}, {%8,%9}, {%0,%1,%2,%3};"
                 : "+f"(d[0]), "+f"(d[1]), "+f"(d[2]), "+f"(d[3])
                 : "r"(a[0]), "r"(a[1]), "r"(a[2]), "r"(a[3]), "r"(b[0]), "r"(b[1]));
}
__device__ __forceinline__ void cp16(uint32_t dst, const void* src) {
    asm volatile("cp.async.cg.shared.global [%0], [%1], 16;" :: "r"(dst), "l"(src));
}

// ---------------- index dtype detection ----------------
__global__ void detect_k(const int* ei) {
    int allz = 1;
    for (int i = 1; i < 512; i += 2)
        if (ei[i] != 0) { allz = 0; break; }
    g_idx64 = allz;
}
__device__ __forceinline__ int load_index(const void* p, long long i, int is64) {
    if (is64) return (int)((const long long*)p)[i];
    return ((const int*)p)[i];
}

// ---------------- CSR build ----------------
__global__ void hist_k(const void* ei) {
    int e = blockIdx.x * 256 + threadIdx.x;
    if (e >= EE) return;
    int dst = load_index(ei, EE + e, g_idx64);
    atomicAdd(&g_deg[dst], 1);
}
__global__ void scan1_k() {
    __shared__ int sm[256];
    int i = blockIdx.x * 256 + threadIdx.x;
    sm[threadIdx.x] = (i < NN) ? g_deg[i] : 0;
    __syncthreads();
    for (int st = 128; st > 0; st >>= 1) {
        if (threadIdx.x < st) sm[threadIdx.x] += sm[threadIdx.x + st];
        __syncthreads();
    }
    if (threadIdx.x == 0) g_part[blockIdx.x] = sm[0];
}
__global__ void scan2_k(int nb) {      // parallel exclusive scan of partials
    __shared__ int sm[256];
    int t = threadIdx.x;
    int v = (t < nb) ? g_part[t] : 0;
    sm[t] = v;
    __syncthreads();
    for (int st = 1; st < 256; st <<= 1) {
        int u = (t >= st) ? sm[t - st] : 0;
        __syncthreads();
        sm[t] += u;
        __syncthreads();
    }
    if (t < nb) g_part[t] = sm[t] - v;
    if (t == 0) g_off[NN] = EE;
}
__global__ void scan3_k() {
    __shared__ int sm[256];
    int i = blockIdx.x * 256 + threadIdx.x;
    int v = (i < NN) ? g_deg[i] : 0;
    sm[threadIdx.x] = v;
    __syncthreads();
    for (int st = 1; st < 256; st <<= 1) {
        int t = (threadIdx.x >= st) ? sm[threadIdx.x - st] : 0;
        __syncthreads();
        sm[threadIdx.x] += t;
        __syncthreads();
    }
    if (i < NN) {
        int off = g_part[blockIdx.x] + sm[threadIdx.x] - v;
        g_off[i] = off;
        g_wp[i]  = off;
    }
}
__global__ void fill_k(const void* ei) {
    int e = blockIdx.x * 256 + threadIdx.x;
    if (e >= EE) return;
    int is64 = g_idx64;
    int src = load_index(ei, e, is64);
    int dst = load_index(ei, EE + e, is64);
    int p = atomicAdd(&g_wp[dst], 1);
    g_srcs[p] = src;
}

// ---------------- BN finalize: stats -> (sc, sh) ----------------
__global__ void finalize_k(const float* __restrict__ gamma, const float* __restrict__ beta) {
    int c = threadIdx.x;
    const float invn = 1.f / (float)NN;
    float mean = g_stats[c] * invn;
    float var  = g_stats[256 + c] * invn - mean * mean;
    float sc   = gamma[c] * rsqrtf(var + BN_EPS);
    g_scsh[c]       = sc;
    g_scsh[256 + c] = beta[c] - mean * sc;
}

// ---------------- aggregation ----------------
// agg[r] = sum_{j in {r} u N(r)} BN(x[j]) = sc (.) sum_raw + cnt*sh  (BN=true)
// BN=false: raw sum (layer 0, input has no preceding BN).
template<int DIMV, bool BN>
__global__ void agg_k(const float* __restrict__ x, float* __restrict__ agg) {
    constexpr int RPB = 256 / DIMV;
    int r = blockIdx.x * RPB + threadIdx.x / DIMV;
    int c = threadIdx.x & (DIMV - 1);
    if (r >= NN) return;
    const float4* x4 = (const float4*)x;
    float4 s = x4[(size_t)r * DIMV + c];
    int i0 = g_off[r], i1 = g_off[r + 1];
    int i = i0;
    for (; i + 4 <= i1; i += 4) {
        int s0 = g_srcs[i], s1 = g_srcs[i + 1], s2 = g_srcs[i + 2], s3 = g_srcs[i + 3];
        float4 v0 = __ldg(&x4[(size_t)s0 * DIMV + c]);
        float4 v1 = __ldg(&x4[(size_t)s1 * DIMV + c]);
        float4 v2 = __ldg(&x4[(size_t)s2 * DIMV + c]);
        float4 v3 = __ldg(&x4[(size_t)s3 * DIMV + c]);
        s.x += v0.x + v1.x + v2.x + v3.x;
        s.y += v0.y + v1.y + v2.y + v3.y;
        s.z += v0.z + v1.z + v2.z + v3.z;
        s.w += v0.w + v1.w + v2.w + v3.w;
    }
    for (; i < i1; i++) {
        float4 v = __ldg(&x4[(size_t)g_srcs[i] * DIMV + c]);
        s.x += v.x; s.y += v.y; s.z += v.z; s.w += v.w;
    }
    if (BN) {
        float cnt = (float)(i1 - i0 + 1);
        float4 sc = ((const float4*)g_scsh)[c];
        float4 sh = ((const float4*)g_scsh)[64 + c];
        s.x = fmaf(sc.x, s.x, cnt * sh.x);
        s.y = fmaf(sc.y, s.y, cnt * sh.y);
        s.z = fmaf(sc.z, s.z, cnt * sh.z);
        s.w = fmaf(sc.w, s.w, cnt * sh.w);
    }
    ((float4*)agg)[(size_t)r * DIMV + c] = s;
}

// ---------------- weight pre-split ----------------
__global__ void convw_k(const float* __restrict__ w, uint32_t* __restrict__ bhi,
                        uint32_t* __restrict__ blo, int kpc) {
    int t = blockIdx.x * 256 + threadIdx.x;
    if (t >= 256 * kpc) return;
    int n = t / kpc, kp = t - n * kpc;
    float e = w[(2 * kp)     * 256 + n];
    float o = w[(2 * kp + 1) * 256 + n];
    uint32_t h, l;
    split2(e, o, h, l);
    bhi[n * kpc + kp] = h;
    blo[n * kpc + kp] = l;
}

// ---------------- bf16x3 tensor GEMM: C = relu(A @ B + bias) [+ BN stats] ----------------
template<int K, bool STATS>
__global__ void __launch_bounds__(256)
gemm_bf(const float* __restrict__ A, const uint32_t* __restrict__ Bhi,
        const uint32_t* __restrict__ Blo, const float* __restrict__ bias,
        float* __restrict__ C) {
    constexpr int NT = K / 16, KP = K / 2;
    __shared__ uint32_t As_hi[128][12], As_lo[128][12];
    __shared__ uint32_t Bs_hi[2][128][12], Bs_lo[2][128][12];

    const int tid  = threadIdx.x;
    const int lane = tid & 31, w = tid >> 5;
    const int wm = (w >> 2) * 64, wn = (w & 3) * 32;
    const int m0 = blockIdx.x * 128, n0 = blockIdx.y * 128;
    const int lq = lane >> 2, lr = lane & 3;
    const int arow = tid >> 1, akh = tid & 1;
    const bool avalid = (m0 + arow) < NN;

    float acc[4][4][4];
#pragma unroll
    for (int i = 0; i < 4; i++)
#pragma unroll
        for (int j = 0; j < 4; j++)
#pragma unroll
            for (int r = 0; r < 4; r++) acc[i][j][r] = 0.f;

    float rA[8];
    auto ldgA = [&](int kt) {
        if (avalid) {
            const float4* p = (const float4*)(A + (size_t)(m0 + arow) * K + kt * 16 + akh * 8);
            float4 v0 = __ldg(p), v1 = __ldg(p + 1);
            rA[0] = v0.x; rA[1] = v0.y; rA[2] = v0.z; rA[3] = v0.w;
            rA[4] = v1.x; rA[5] = v1.y; rA[6] = v1.z; rA[7] = v1.w;
        } else {
#pragma unroll
            for (int j = 0; j < 8; j++) rA[j] = 0.f;
        }
    };
    auto stsA = [&]() {
        uint32_t h[4], l[4];
#pragma unroll
        for (int j = 0; j < 4; j++) split2(rA[2 * j], rA[2 * j + 1], h[j], l[j]);
        *(uint4*)&As_hi[arow][akh * 4] = make_uint4(h[0], h[1], h[2], h[3]);
        *(uint4*)&As_lo[arow][akh * 4] = make_uint4(l[0], l[1], l[2], l[3]);
    };
    auto cpB = [&](int kt, int s) {
        size_t o = (size_t)(n0 + arow) * KP + kt * 8 + akh * 4;
        cp16((uint32_t)__cvta_generic_to_shared(&Bs_hi[s][arow][akh * 4]), Bhi + o);
        cp16((uint32_t)__cvta_generic_to_shared(&Bs_lo[s][arow][akh * 4]), Blo + o);
    };

    ldgA(0);
    cpB(0, 0);
    asm volatile("cp.async.commit_group;");

    for (int kt = 0; kt < NT; kt++) {
        const int s = kt & 1;
        stsA();
        if (kt + 1 < NT) ldgA(kt + 1);
        asm volatile("cp.async.wait_group 0;");
        __syncthreads();
        if (kt + 1 < NT) {
            cpB(kt + 1, s ^ 1);
            asm volatile("cp.async.commit_group;");
        }
        uint32_t ah[4][4], al[4][4], bh[4][2], bl[4][2];
#pragma unroll
        for (int mi = 0; mi < 4; mi++) {
            int r = wm + mi * 16 + lq;
            ah[mi][0] = As_hi[r][lr];     ah[mi][1] = As_hi[r + 8][lr];
            ah[mi][2] = As_hi[r][lr + 4]; ah[mi][3] = As_hi[r + 8][lr + 4];
            al[mi][0] = As_lo[r][lr];     al[mi][1] = As_lo[r + 8][lr];
            al[mi][2] = As_lo[r][lr + 4]; al[mi][3] = As_lo[r + 8][lr + 4];
        }
#pragma unroll
        for (int ni = 0; ni < 4; ni++) {
            int c = wn + ni * 8 + lq;
            bh[ni][0] = Bs_hi[s][c][lr]; bh[ni][1] = Bs_hi[s][c][lr + 4];
            bl[ni][0] = Bs_lo[s][c][lr]; bl[ni][1] = Bs_lo[s][c][lr + 4];
        }
#pragma unroll
        for (int mi = 0; mi < 4; mi++)
#pragma unroll
            for (int ni = 0; ni < 4; ni++) {
                mma_bf16(acc[mi][ni], ah[mi], bh[ni]);
                mma_bf16(acc[mi][ni], al[mi], bh[ni]);
                mma_bf16(acc[mi][ni], ah[mi], bl[ni]);
            }
        __syncthreads();
    }

    // epilogue: bias + relu (+ column stats)
    float cs[8], cq[8];
#pragma unroll
    for (int j = 0; j < 8; j++) { cs[j] = 0.f; cq[j] = 0.f; }

#pragma unroll
    for (int mi = 0; mi < 4; mi++)
#pragma unroll
        for (int half = 0; half < 2; half++) {
            int row = m0 + wm + mi * 16 + lq + half * 8;
            if (row < NN) {
#pragma unroll
                for (int ni = 0; ni < 4; ni++) {
                    int col = n0 + wn + ni * 8 + 2 * lr;
                    float2 bv = *(const float2*)&bias[col];
                    float v0 = fmaxf(acc[mi][ni][half * 2 + 0] + bv.x, 0.f);
                    float v1 = fmaxf(acc[mi][ni][half * 2 + 1] + bv.y, 0.f);
                    if (STATS) {
                        cs[ni * 2 + 0] += v0; cq[ni * 2 + 0] += v0 * v0;
                        cs[ni * 2 + 1] += v1; cq[ni * 2 + 1] += v1 * v1;
                    }
                    *(float2*)&C[(size_t)row * 256 + col] = make_float2(v0, v1);
                }
            }
        }

    if (STATS) {
#pragma unroll
        for (int j = 0; j < 8; j++) {
#pragma unroll
            for (int o = 4; o < 32; o <<= 1) {
                cs[j] += __shfl_xor_sync(0xffffffffu, cs[j], o);
                cq[j] += __shfl_xor_sync(0xffffffffu, cq[j], o);
            }
        }
        if (lq == 0) {
#pragma unroll
            for (int j = 0; j < 8; j++) {
                int col = n0 + wn + (j >> 1) * 8 + 2 * lr + (j & 1);
                atomicAdd(&g_stats[col], cs[j]);
                atomicAdd(&g_stats[256 + col], cq[j]);
            }
        }
    }
}

// ---------------- global add pool with fused BN ----------------
__device__ int lower_bound_g(const void* b, int v, int is64) {
    int lo = 0, hi = NN;
    while (lo < hi) {
        int mid = (lo + hi) >> 1;
        if (load_index(b, mid, is64) < v) lo = mid + 1; else hi = mid;
    }
    return lo;
}
__global__ void pool_k(const float* __restrict__ h, const void* __restrict__ batch,
                       float* __restrict__ out) {
    __shared__ int slo, shi;
    int g = blockIdx.x;
    if (threadIdx.x == 0) {
        int is64 = g_idx64;
        slo = lower_bound_g(batch, g, is64);
        shi = lower_bound_g(batch, g + 1, is64);
    }
    __syncthreads();
    int c = threadIdx.x;
    float s = 0.f;
    int r = slo;
    for (; r + 2 <= shi; r += 2)
        s += h[(size_t)r * 256 + c] + h[(size_t)(r + 1) * 256 + c];
    if (r < shi) s += h[(size_t)r * 256 + c];
    // pooled BN: sum BN(h) = sc*sum + count*sh
    out[g * 256 + c] = fmaf(g_scsh[c], s, (float)(shi - slo) * g_scsh[256 + c]);
}

// ---------------- launch ----------------
extern "C" void kernel_launch(void* const* d_in, const int* in_sizes, int n_in,
                              void* d_out, int out_size) {
    const float* x     = (const float*)d_in[0];
    const void*  ei    = d_in[1];
    const void*  batch = d_in[2];

    float *agg, *hid, *h2, *stats;
    uint32_t *bhi, *blo;
    int *deg;
    cudaGetSymbolAddress((void**)&agg,   g_agg);
    cudaGetSymbolAddress((void**)&hid,   g_hid);
    cudaGetSymbolAddress((void**)&h2,    g_h2);
    cudaGetSymbolAddress((void**)&stats, g_stats);
    cudaGetSymbolAddress((void**)&bhi,   g_bhi);
    cudaGetSymbolAddress((void**)&blo,   g_blo);
    cudaGetSymbolAddress((void**)&deg,   g_deg);

    detect_k<<<1, 1>>>((const int*)ei);

    // CSR build
    const int NB = (NN + 255) / 256;
    cudaMemsetAsync(deg, 0, NN * sizeof(int));
    hist_k<<<(EE + 255) / 256, 256>>>(ei);
    scan1_k<<<NB, 256>>>();
    scan2_k<<<1, 256>>>(NB);
    scan3_k<<<NB, 256>>>();
    fill_k<<<(EE + 255) / 256, 256>>>(ei);

    // pre-split all weights
    for (int l = 0; l < 3; l++) {
        int k1 = (l == 0) ? FF : DD;
        convw_k<<<(256 * (k1 / 2) + 255) / 256, 256>>>(
            (const float*)d_in[3 + 6 * l], bhi + (2 * l) * 256 * 128,
            blo + (2 * l) * 256 * 128, k1 / 2);
        convw_k<<<(256 * 128 + 255) / 256, 256>>>(
            (const float*)d_in[5 + 6 * l], bhi + (2 * l + 1) * 256 * 128,
            blo + (2 * l + 1) * 256 * 128, 128);
    }

    for (int l = 0; l < 3; l++) {
        const float* b1    = (const float*)d_in[4 + 6 * l];
        const float* b2    = (const float*)d_in[6 + 6 * l];
        const float* gamma = (const float*)d_in[7 + 6 * l];
        const float* beta  = (const float*)d_in[8 + 6 * l];

        // aggregation (fused BN-apply of previous layer for l>0)
        if (l == 0)      agg_k<32, false><<<(NN + 7) / 8, 256>>>(x, agg);
        else             agg_k<64, true ><<<(NN + 3) / 4, 256>>>(h2, agg);

        dim3 gg((NN + 127) / 128, 2);
        const uint32_t* w1h = bhi + (2 * l) * 256 * 128;
        const uint32_t* w1l = blo + (2 * l) * 256 * 128;
        const uint32_t* w2h = bhi + (2 * l + 1) * 256 * 128;
        const uint32_t* w2l = blo + (2 * l + 1) * 256 * 128;
        if (l == 0) gemm_bf<128, false><<<gg, 256>>>(agg, w1h, w1l, b1, hid);
        else        gemm_bf<256, false><<<gg, 256>>>(agg, w1h, w1l, b1, hid);

        cudaMemsetAsync(stats, 0, 2 * DD * sizeof(float));
        gemm_bf<256, true><<<gg, 256>>>(hid, w2h, w2l, b2, h2);
        finalize_k<<<1, 256>>>(gamma, beta);
    }

    pool_k<<<GG, 256>>>(h2, batch, (float*)d_out);
}